// round 12
// baseline (speedup 1.0000x reference)
#include <cuda_runtime.h>
#include <math.h>

#define EPSF 1e-6f
#define HANDS 64    // per block: 2 hands per thread
#define BLKT 160    // 32 lanes x 5 finger-warps

struct V3 { float x, y, z; };

__device__ __forceinline__ V3 operator+(V3 a, V3 b){ return {a.x+b.x, a.y+b.y, a.z+b.z}; }
__device__ __forceinline__ V3 operator-(V3 a, V3 b){ return {a.x-b.x, a.y-b.y, a.z-b.z}; }
__device__ __forceinline__ V3 operator*(V3 a, float s){ return {a.x*s, a.y*s, a.z*s}; }
__device__ __forceinline__ float dot3(V3 a, V3 b){ return a.x*b.x + a.y*b.y + a.z*b.z; }
__device__ __forceinline__ V3 cross3(V3 a, V3 b){
    return { a.y*b.z - a.z*b.y, a.z*b.x - a.x*b.z, a.x*b.y - a.y*b.x };
}
__device__ __forceinline__ float nrm3(V3 a){ return sqrtf(dot3(a,a)); }
// EXACT reference semantics: v / (|v| + 1e-6); the additive eps is load-bearing.
__device__ __forceinline__ V3 unitv(V3 a){
    float inv = __fdividef(1.0f, nrm3(a)+EPSF); return a*inv;
}
__device__ __forceinline__ float clampd(float x){ return fminf(fmaxf(x, -1.0f+EPSF), 1.0f-EPSF); }

struct M3 { float a[9]; };

__device__ __forceinline__ V3 mv(const M3& R, V3 v){
    return { R.a[0]*v.x + R.a[1]*v.y + R.a[2]*v.z,
             R.a[3]*v.x + R.a[4]*v.y + R.a[5]*v.z,
             R.a[6]*v.x + R.a[7]*v.y + R.a[8]*v.z };
}

__device__ __forceinline__ V3 ld3p(const float* p){ return { p[0], p[1], p[2] }; }
__device__ __forceinline__ void st3p(float* p, V3 v){ p[0] = v.x; p[1] = v.y; p[2] = v.z; }

// per-finger tables
__constant__ int   cMCP[5] = {1, 4, 10, 7, 13};
__constant__ int   cTIP[5] = {17, 18, 19, 20, 16};
__constant__ int   cPB [5] = {4, 10, 7, 1, 1};
__constant__ float cRC [5] = {0.98219268f, 0.99115533f, 0.98890531f, 0.99939799f, 1.0f};
__constant__ float cRS [5] = {0.18787768f, 0.13270742f, -0.14855814f, 0.03469304f, 0.0f};

__device__ __forceinline__ M3 rotmat_u(V3 a, float c, float s){
    float C = 1.0f - c;
    M3 R;
    R.a[0] = c + a.x*a.x*C;     R.a[1] = a.x*a.y*C - a.z*s; R.a[2] = a.x*a.z*C + a.y*s;
    R.a[3] = a.y*a.x*C + a.z*s; R.a[4] = c + a.y*a.y*C;     R.a[5] = a.y*a.z*C - a.x*s;
    R.a[6] = a.z*a.x*C - a.y*s; R.a[7] = a.z*a.y*C + a.x*s; R.a[8] = c + a.z*a.z*C;
    return R;
}

// Sign-resolved rotation: |d0|>|d1| <=> t1*t2>0 ; reference picks R(-) on tie.
__device__ __forceinline__ M3 pick_rot(V3 a, float c, float s, V3 sv, V3 ev){
    float C  = 1.0f - c;
    float t1 = c*dot3(sv, ev) + C*dot3(a, sv)*dot3(a, ev);
    float t2 = s*dot3(cross3(a, sv), ev);
    if (!(t1*t2 > 0.0f)) s = -s;
    return rotmat_u(a, c, s);
}

__device__ __forceinline__ M3 getrot(float angle, float flexRatio, V3 axisU, V3 sv, V3 ev){
    const float ANGLEP = 0.34906585039886590f;  // pi/9
    const float TH120  = 2.09439506666666650f;  // 3.1415926/180*120
    angle = (angle > TH120) ? (3.1415926f - angle) : angle;
    float dif = fmaxf(angle - ANGLEP, 0.0f) * flexRatio;
    float s, c;
    sincosf(dif, &s, &c);
    return pick_rot(axisU, c, s, sv, ev);
}

// Smallest eigenvector of symmetric 3x3 (analytic + one Rayleigh refinement).
__device__ __forceinline__ V3 smallest_evec(float a00, float a01, float a02,
                                            float a11, float a12, float a22){
    float m   = (a00 + a11 + a22) * (1.0f/3.0f);
    float b00 = a00 - m, b11 = a11 - m, b22 = a22 - m;
    float p1  = a01*a01 + a02*a02 + a12*a12;
    float p2  = b00*b00 + b11*b11 + b22*b22 + 2.0f*p1;
    float p   = sqrtf(fmaxf(p2*(1.0f/6.0f), 1e-30f));
    float invp = __fdividef(1.0f, p);
    float det = b00*(b11*b22 - a12*a12)
              - a01*(a01*b22 - a12*a02)
              + a02*(a01*a12 - b11*a02);
    float r = det * 0.5f * invp*invp*invp;
    r = fminf(fmaxf(r, -1.0f), 1.0f);
    float phi = acosf(r) * (1.0f/3.0f);
    float lam = m + 2.0f*p*cosf(phi + 2.0943951023931953f);

    V3 v;
    #pragma unroll
    for (int it = 0; it < 2; it++) {
        V3 r0 = { a00 - lam, a01, a02 };
        V3 r1 = { a01, a11 - lam, a12 };
        V3 r2 = { a02, a12, a22 - lam };
        V3 c0 = cross3(r0, r1), c1 = cross3(r0, r2), c2 = cross3(r1, r2);
        float l0 = dot3(c0,c0), l1 = dot3(c1,c1), l2 = dot3(c2,c2);
        V3 best = c0; float lb = l0;
        if (l1 > lb) { best = c1; lb = l1; }
        if (l2 > lb) { best = c2; lb = l2; }
        v = best * rsqrtf(fmaxf(lb, 1e-30f));
        if (it < 1) {
            float Av0 = a00*v.x + a01*v.y + a02*v.z;
            float Av1 = a01*v.x + a11*v.y + a12*v.z;
            float Av2 = a02*v.x + a12*v.y + a22*v.z;
            lam = v.x*Av0 + v.y*Av1 + v.z*Av2;
        }
    }
    return v;
}

__device__ __forceinline__ void plan4(V3& p0, V3& p1, V3& p2, V3& p3){
    V3 cm = (p0 + p1 + p2 + p3) * 0.25f;
    V3 d0 = p0 - cm, d1 = p1 - cm, d2 = p2 - cm, d3 = p3 - cm;
    float a00 = d0.x*d0.x + d1.x*d1.x + d2.x*d2.x + d3.x*d3.x;
    float a01 = d0.x*d0.y + d1.x*d1.y + d2.x*d2.y + d3.x*d3.y;
    float a02 = d0.x*d0.z + d1.x*d1.z + d2.x*d2.z + d3.x*d3.z;
    float a11 = d0.y*d0.y + d1.y*d1.y + d2.y*d2.y + d3.y*d3.y;
    float a12 = d0.y*d0.z + d1.y*d1.z + d2.y*d2.z + d3.y*d3.z;
    float a22 = d0.z*d0.z + d1.z*d1.z + d2.z*d2.z + d3.z*d3.z;
    V3 n = smallest_evec(a00, a01, a02, a11, a12, a22);
    float vd = -dot3(n, cm);
    float t;
    t = dot3(p0, n) + vd; p0 = p0 - n*t;
    t = dot3(p1, n) + vd; p1 = p1 - n*t;
    t = dot3(p2, n) + vd; p2 = p2 - n*t;
    t = dot3(p3, n) + vd; p3 = p3 - n*t;
}

__device__ __forceinline__ void abduct(V3 palm, V3 wristmcp,
                                       float rectC, float rectS,
                                       V3 mcp, V3& pip, V3& dip, V3& tip){
    float vd   = -dot3(mcp, palm);
    float dist = dot3(pip, palm) + vd;
    V3 projpip = pip - palm*dist;

    V3 d  = pip - mcp;
    float dis = nrm3(d);
    float invdis = __fdividef(1.0f, dis + EPSF);
    V3 mcppip = d * invdis;

    V3 e  = projpip - mcp;
    float lene = nrm3(e);
    V3 mcpproj = e * __fdividef(1.0f, lene + EPSF);
    float flex = lene * invdis;
    flex = (flex < 0.3f) ? 0.0f : flex;

    float cv = clampd(dot3(wristmcp, mcppip));
    bool overflex = cv < 0.00079632671073326f;   // == acos(cv) > 1.57

    float Cr = 1.0f - rectC;
    V3 axw = cross3(palm, wristmcp);
    float adw = dot3(palm, wristmcp);
    V3 rect = wristmcp*rectC + axw*rectS + palm*(adw*Cr);

    float ang = acosf(clampd(dot3(rect, mcpproj)));
    if (overflex) ang = 0.0f;
    M3 R = getrot(ang, flex, palm, mcpproj, wristmcp);

    pip = mv(R, pip - mcp) + mcp;
    dip = mv(R, dip - mcp) + mcp;
    tip = mv(R, tip - mcp) + mcp;
}

__device__ __forceinline__ void planerot(V3 palm, V3 wristmcp,
                                         V3 mcp, V3 pip, V3& dip, V3& tip){
    const float COS_TH120 = -0.49999997f;
    const float cAP = 0.93969262078590838f;
    const float sAP = 0.34202014332566871f;

    V3 mcppip = unitv(pip - mcp);
    V3 pipdip = unitv(dip - pip);
    bool maskline = fabsf(dot3(mcppip, pipdip)) > 0.95f;
    V3 cdir = unitv(cross3(mcppip, pipdip));
    V3 stdv = unitv(cross3(wristmcp, palm));

    float x = clampd(dot3(cdir, stdv));
    float ca = (x < COS_TH120) ? -x : x;
    float sa = sqrtf(fmaxf(1.0f - x*x, 0.0f));
    if (maskline) { ca = 1.0f; sa = 0.0f; }

    float c, s;
    if (ca >= cAP) { c = 1.0f; s = 0.0f; }
    else { c = ca*cAP + sa*sAP; s = sa*cAP - ca*sAP; }
    M3 R = pick_rot(mcppip, c, s, cdir, stdv);

    dip = mv(R, dip - pip) + pip;
    tip = mv(R, tip - pip) + pip;
}

__global__ void __launch_bounds__(BLKT, 4)
handpose_kernel(const float* __restrict__ in, float* __restrict__ out, int N){
    __shared__ float s[HANDS * 63];
    int base = blockIdx.x * HANDS;
    int nE = N - base; if (nE > HANDS) nE = HANDS;
    int nF = nE * 63;
    const float* gin = in + (long long)base * 63;

    if (nE == HANDS) {
        const float4* g4 = (const float4*)gin;   // base*63*4 B divisible by 16
        float4* s4 = (float4*)s;
        for (int k = threadIdx.x; k < (HANDS*63)/4; k += BLKT)
            s4[k] = g4[k];
    } else {
        for (int k = threadIdx.x; k < nF; k += BLKT) s[k] = gin[k];
    }
    __syncthreads();

    int lane = threadIdx.x & 31;   // hand pair: (lane, lane+32)
    int f    = threadIdx.x >> 5;   // finger (uniform per warp)
    bool thumb = (f == 4);
    bool act0 = lane < nE;
    bool act1 = lane + 32 < nE;

    int oM = 3*cMCP[f], oT = 3*cTIP[f], oB = 3*cPB[f];
    float rc = cRC[f], rs = cRS[f];

    float* sp0 = s + lane * 63;
    float* sp1 = sp0 + 32 * 63;

    V3 w0, m0, p0, d0, t0;
    V3 w1, m1, p1, d1, t1;

    // ---- load + planarize #1 (two independent chains) ----
    if (act0) {
        w0 = ld3p(sp0);
        m0 = ld3p(sp0 + oM); p0 = ld3p(sp0 + oM + 3); d0 = ld3p(sp0 + oM + 6); t0 = ld3p(sp0 + oT);
        plan4(m0, p0, d0, t0);
        st3p(sp0 + oM, m0);
    }
    if (act1) {
        w1 = ld3p(sp1);
        m1 = ld3p(sp1 + oM); p1 = ld3p(sp1 + oM + 3); d1 = ld3p(sp1 + oM + 6); t1 = ld3p(sp1 + oT);
        plan4(m1, p1, d1, t1);
        st3p(sp1 + oM, m1);
    }
    __syncthreads();

    // ---- abduction + planerot (independent chains; no plan#2: provable no-op) ----
    if (act0) {
        V3 pbv = ld3p(sp0 + oB);
        V3 pa = m0 - w0;
        V3 palm = unitv(cross3(pa, pbv - w0));
        V3 wm = unitv(pa);
        abduct(palm, wm, rc, rs, m0, p0, d0, t0);
        if (!thumb) planerot(palm, wm, m0, p0, d0, t0);
        st3p(sp0 + oM, m0); st3p(sp0 + oM + 3, p0); st3p(sp0 + oM + 6, d0); st3p(sp0 + oT, t0);
    }
    if (act1) {
        V3 pbv = ld3p(sp1 + oB);
        V3 pa = m1 - w1;
        V3 palm = unitv(cross3(pa, pbv - w1));
        V3 wm = unitv(pa);
        abduct(palm, wm, rc, rs, m1, p1, d1, t1);
        if (!thumb) planerot(palm, wm, m1, p1, d1, t1);
        st3p(sp1 + oM, m1); st3p(sp1 + oM + 3, p1); st3p(sp1 + oM + 6, d1); st3p(sp1 + oT, t1);
    }
    __syncthreads();

    float* gout = out + (long long)base * 63;
    if (nE == HANDS) {
        const float4* s4 = (const float4*)s;
        float4* g4 = (float4*)gout;
        for (int k = threadIdx.x; k < (HANDS*63)/4; k += BLKT)
            g4[k] = s4[k];
    } else {
        for (int k = threadIdx.x; k < nF; k += BLKT) gout[k] = s[k];
    }
}

extern "C" void kernel_launch(void* const* d_in, const int* in_sizes, int n_in,
                              void* d_out, int out_size){
    const float* in = (const float*)d_in[0];
    float* out = (float*)d_out;
    int N = in_sizes[0] / 63;
    int grid = (N + HANDS - 1) / HANDS;
    handpose_kernel<<<grid, BLKT>>>(in, out, N);
}

// round 13
// speedup vs baseline: 1.3841x; 1.3841x over previous
#include <cuda_runtime.h>
#include <math.h>

#define EPSF 1e-6f
#define HANDS 32
#define BLKT 160   // 32 hands x 5 finger-warps

struct V3 { float x, y, z; };

__device__ __forceinline__ V3 operator+(V3 a, V3 b){ return {a.x+b.x, a.y+b.y, a.z+b.z}; }
__device__ __forceinline__ V3 operator-(V3 a, V3 b){ return {a.x-b.x, a.y-b.y, a.z-b.z}; }
__device__ __forceinline__ V3 operator*(V3 a, float s){ return {a.x*s, a.y*s, a.z*s}; }
__device__ __forceinline__ float dot3(V3 a, V3 b){ return a.x*b.x + a.y*b.y + a.z*b.z; }
__device__ __forceinline__ V3 cross3(V3 a, V3 b){
    return { a.y*b.z - a.z*b.y, a.z*b.x - a.x*b.z, a.x*b.y - a.y*b.x };
}
__device__ __forceinline__ float nrm3(V3 a){ return sqrtf(dot3(a,a)); }
// EXACT reference semantics: v / (|v| + 1e-6); the additive eps is load-bearing.
__device__ __forceinline__ V3 unitv(V3 a){
    float inv = __fdividef(1.0f, nrm3(a)+EPSF); return a*inv;
}
__device__ __forceinline__ float clampd(float x){ return fminf(fmaxf(x, -1.0f+EPSF), 1.0f-EPSF); }

struct M3 { float a[9]; };

__device__ __forceinline__ V3 mv(const M3& R, V3 v){
    return { R.a[0]*v.x + R.a[1]*v.y + R.a[2]*v.z,
             R.a[3]*v.x + R.a[4]*v.y + R.a[5]*v.z,
             R.a[6]*v.x + R.a[7]*v.y + R.a[8]*v.z };
}

__device__ __forceinline__ V3 ld3p(const float* p){ return { p[0], p[1], p[2] }; }
__device__ __forceinline__ void st3p(float* p, V3 v){ p[0] = v.x; p[1] = v.y; p[2] = v.z; }

// per-finger tables
__constant__ int   cMCP[5] = {1, 4, 10, 7, 13};
__constant__ int   cTIP[5] = {17, 18, 19, 20, 16};
__constant__ int   cPB [5] = {4, 10, 7, 1, 1};
__constant__ float cRC [5] = {0.98219268f, 0.99115533f, 0.98890531f, 0.99939799f, 1.0f};
__constant__ float cRS [5] = {0.18787768f, 0.13270742f, -0.14855814f, 0.03469304f, 0.0f};

__device__ __forceinline__ M3 rotmat_u(V3 a, float c, float s){
    float C = 1.0f - c;
    M3 R;
    R.a[0] = c + a.x*a.x*C;     R.a[1] = a.x*a.y*C - a.z*s; R.a[2] = a.x*a.z*C + a.y*s;
    R.a[3] = a.y*a.x*C + a.z*s; R.a[4] = c + a.y*a.y*C;     R.a[5] = a.y*a.z*C - a.x*s;
    R.a[6] = a.z*a.x*C - a.y*s; R.a[7] = a.z*a.y*C + a.x*s; R.a[8] = c + a.z*a.z*C;
    return R;
}

// Sign-resolved rotation: |d0|>|d1| <=> t1*t2>0 ; reference picks R(-) on tie.
__device__ __forceinline__ M3 pick_rot(V3 a, float c, float s, V3 sv, V3 ev){
    float C  = 1.0f - c;
    float t1 = c*dot3(sv, ev) + C*dot3(a, sv)*dot3(a, ev);
    float t2 = s*dot3(cross3(a, sv), ev);
    if (!(t1*t2 > 0.0f)) s = -s;
    return rotmat_u(a, c, s);
}

// getrot for abduction: hardware MUFU sin/cos (dif in [0,pi), abs err ~2^-21 —
// a smooth ~1e-6 perturbation, NOT an epsilon-semantics change)
__device__ __forceinline__ M3 getrot(float angle, float flexRatio, V3 axisU, V3 sv, V3 ev){
    const float ANGLEP = 0.34906585039886590f;  // pi/9
    const float TH120  = 2.09439506666666650f;  // 3.1415926/180*120
    angle = (angle > TH120) ? (3.1415926f - angle) : angle;
    float dif = fmaxf(angle - ANGLEP, 0.0f) * flexRatio;
    float s = __sinf(dif);
    float c = __cosf(dif);
    return pick_rot(axisU, c, s, sv, ev);
}

// Smallest eigenvector of symmetric 3x3 (analytic + one Rayleigh refinement;
// __cosf's ~1e-6 lambda error is quadratically corrected by the refinement).
__device__ __forceinline__ V3 smallest_evec(float a00, float a01, float a02,
                                            float a11, float a12, float a22){
    float m   = (a00 + a11 + a22) * (1.0f/3.0f);
    float b00 = a00 - m, b11 = a11 - m, b22 = a22 - m;
    float p1  = a01*a01 + a02*a02 + a12*a12;
    float p2  = b00*b00 + b11*b11 + b22*b22 + 2.0f*p1;
    float p   = sqrtf(fmaxf(p2*(1.0f/6.0f), 1e-30f));
    float invp = __fdividef(1.0f, p);
    float det = b00*(b11*b22 - a12*a12)
              - a01*(a01*b22 - a12*a02)
              + a02*(a01*a12 - b11*a02);
    float r = det * 0.5f * invp*invp*invp;
    r = fminf(fmaxf(r, -1.0f), 1.0f);
    float phi = acosf(r) * (1.0f/3.0f);
    float lam = m + 2.0f*p*__cosf(phi + 2.0943951023931953f);

    V3 v;
    #pragma unroll
    for (int it = 0; it < 2; it++) {
        V3 r0 = { a00 - lam, a01, a02 };
        V3 r1 = { a01, a11 - lam, a12 };
        V3 r2 = { a02, a12, a22 - lam };
        V3 c0 = cross3(r0, r1), c1 = cross3(r0, r2), c2 = cross3(r1, r2);
        float l0 = dot3(c0,c0), l1 = dot3(c1,c1), l2 = dot3(c2,c2);
        V3 best = c0; float lb = l0;
        if (l1 > lb) { best = c1; lb = l1; }
        if (l2 > lb) { best = c2; lb = l2; }
        v = best * rsqrtf(fmaxf(lb, 1e-30f));
        if (it < 1) {
            float Av0 = a00*v.x + a01*v.y + a02*v.z;
            float Av1 = a01*v.x + a11*v.y + a12*v.z;
            float Av2 = a02*v.x + a12*v.y + a22*v.z;
            lam = v.x*Av0 + v.y*Av1 + v.z*Av2;
        }
    }
    return v;
}

__device__ __forceinline__ void plan4(V3& p0, V3& p1, V3& p2, V3& p3){
    V3 cm = (p0 + p1 + p2 + p3) * 0.25f;
    V3 d0 = p0 - cm, d1 = p1 - cm, d2 = p2 - cm, d3 = p3 - cm;
    float a00 = d0.x*d0.x + d1.x*d1.x + d2.x*d2.x + d3.x*d3.x;
    float a01 = d0.x*d0.y + d1.x*d1.y + d2.x*d2.y + d3.x*d3.y;
    float a02 = d0.x*d0.z + d1.x*d1.z + d2.x*d2.z + d3.x*d3.z;
    float a11 = d0.y*d0.y + d1.y*d1.y + d2.y*d2.y + d3.y*d3.y;
    float a12 = d0.y*d0.z + d1.y*d1.z + d2.y*d2.z + d3.y*d3.z;
    float a22 = d0.z*d0.z + d1.z*d1.z + d2.z*d2.z + d3.z*d3.z;
    V3 n = smallest_evec(a00, a01, a02, a11, a12, a22);
    float vd = -dot3(n, cm);
    float t;
    t = dot3(p0, n) + vd; p0 = p0 - n*t;
    t = dot3(p1, n) + vd; p1 = p1 - n*t;
    t = dot3(p2, n) + vd; p2 = p2 - n*t;
    t = dot3(p3, n) + vd; p3 = p3 - n*t;
}

__device__ __forceinline__ void abduct(V3 palm, V3 wristmcp,
                                       float rectC, float rectS,
                                       V3 mcp, V3& pip, V3& dip, V3& tip){
    float vd   = -dot3(mcp, palm);
    float dist = dot3(pip, palm) + vd;
    V3 projpip = pip - palm*dist;

    V3 d  = pip - mcp;
    float dis = nrm3(d);
    float invdis = __fdividef(1.0f, dis + EPSF);
    V3 mcppip = d * invdis;

    V3 e  = projpip - mcp;
    float lene = nrm3(e);
    V3 mcpproj = e * __fdividef(1.0f, lene + EPSF);
    float flex = lene * invdis;
    flex = (flex < 0.3f) ? 0.0f : flex;

    float cv = clampd(dot3(wristmcp, mcppip));
    bool overflex = cv < 0.00079632671073326f;   // == acos(cv) > 1.57

    float Cr = 1.0f - rectC;
    V3 axw = cross3(palm, wristmcp);
    float adw = dot3(palm, wristmcp);
    V3 rect = wristmcp*rectC + axw*rectS + palm*(adw*Cr);

    float ang = acosf(clampd(dot3(rect, mcpproj)));
    if (overflex) ang = 0.0f;
    M3 R = getrot(ang, flex, palm, mcpproj, wristmcp);

    pip = mv(R, pip - mcp) + mcp;
    dip = mv(R, dip - mcp) + mcp;
    tip = mv(R, tip - mcp) + mcp;
}

__device__ __forceinline__ void planerot(V3 palm, V3 wristmcp,
                                         V3 mcp, V3 pip, V3& dip, V3& tip){
    const float COS_TH120 = -0.49999997f;
    const float cAP = 0.93969262078590838f;
    const float sAP = 0.34202014332566871f;

    V3 mcppip = unitv(pip - mcp);
    V3 pipdip = unitv(dip - pip);
    bool maskline = fabsf(dot3(mcppip, pipdip)) > 0.95f;
    V3 cdir = unitv(cross3(mcppip, pipdip));
    V3 stdv = unitv(cross3(wristmcp, palm));

    float x = clampd(dot3(cdir, stdv));
    float ca = (x < COS_TH120) ? -x : x;
    float sa = sqrtf(fmaxf(1.0f - x*x, 0.0f));
    if (maskline) { ca = 1.0f; sa = 0.0f; }

    float c, s;
    if (ca >= cAP) { c = 1.0f; s = 0.0f; }
    else { c = ca*cAP + sa*sAP; s = sa*cAP - ca*sAP; }
    M3 R = pick_rot(mcppip, c, s, cdir, stdv);

    dip = mv(R, dip - pip) + pip;
    tip = mv(R, tip - pip) + pip;
}

__global__ void __launch_bounds__(BLKT, 7)
handpose_kernel(const float* __restrict__ in, float* __restrict__ out, int N){
    __shared__ float s[HANDS * 63];
    int base = blockIdx.x * HANDS;
    int nE = N - base; if (nE > HANDS) nE = HANDS;
    int nF = nE * 63;
    const float* gin = in + (long long)base * 63;

    if (nE == HANDS) {
        const float4* g4 = (const float4*)gin;   // base*63*4 B divisible by 16
        float4* s4 = (float4*)s;
        for (int k = threadIdx.x; k < (HANDS*63)/4; k += BLKT)
            s4[k] = g4[k];
    } else {
        for (int k = threadIdx.x; k < nF; k += BLKT) s[k] = gin[k];
    }
    __syncthreads();

    int lane = threadIdx.x & 31;   // hand within block
    int f    = threadIdx.x >> 5;   // finger (uniform per warp)
    bool act = lane < nE;
    bool thumb = (f == 4);
    float* sp = s + lane * 63;

    float* pM = sp + 3*cMCP[f];
    float* pT = sp + 3*cTIP[f];
    float* pB = sp + 3*cPB[f];
    float rc = cRC[f], rs = cRS[f];

    V3 w, mcp, pip, dip, tip;
    if (act) {
        w   = ld3p(sp);
        mcp = ld3p(pM);
        pip = ld3p(pM + 3);
        dip = ld3p(pM + 6);
        tip = ld3p(pT);

        // ---- planarize #1 (registers) ----
        plan4(mcp, pip, dip, tip);
        st3p(pM, mcp);   // publish planarized MCP for neighbor warps
    }
    __syncthreads();

    if (act) {
        V3 pbv = ld3p(pB);    // neighbor MCP (post-plan#1; unchanged by abduction)

        V3 pa = mcp - w;
        V3 palm = unitv(cross3(pa, pbv - w));
        V3 wristmcp = unitv(pa);

        // ---- abduction ----
        abduct(palm, wristmcp, rc, rs, mcp, pip, dip, tip);
        // ---- plane rotation (fingers 0..3) ----
        if (!thumb) planerot(palm, wristmcp, mcp, pip, dip, tip);

        // planarize #2 is a provable no-op (joints remain exactly coplanar).

        st3p(pM,     mcp);
        st3p(pM + 3, pip);
        st3p(pM + 6, dip);
        st3p(pT,     tip);
    }
    __syncthreads();

    float* gout = out + (long long)base * 63;
    if (nE == HANDS) {
        const float4* s4 = (const float4*)s;
        float4* g4 = (float4*)gout;
        for (int k = threadIdx.x; k < (HANDS*63)/4; k += BLKT)
            g4[k] = s4[k];
    } else {
        for (int k = threadIdx.x; k < nF; k += BLKT) gout[k] = s[k];
    }
}

extern "C" void kernel_launch(void* const* d_in, const int* in_sizes, int n_in,
                              void* d_out, int out_size){
    const float* in = (const float*)d_in[0];
    float* out = (float*)d_out;
    int N = in_sizes[0] / 63;
    int grid = (N + HANDS - 1) / HANDS;
    handpose_kernel<<<grid, BLKT>>>(in, out, N);
}